// round 2
// baseline (speedup 1.0000x reference)
#include <cuda_runtime.h>

#define L_SEQ 1024
#define M_DIM 128

// Transposed table: per step i, 128 floats of e0[m] = eps[0,m,i],
// then 128 floats of dlt[m] = eps[1,m,i] - eps[0,m,i].  1 MB, L2-resident.
__device__ float g_tbl[L_SEQ * 256];

typedef unsigned long long u64;

__device__ __forceinline__ u64 pk2(float lo, float hi) {
    u64 r; asm("mov.b64 %0,{%1,%2};" : "=l"(r) : "f"(lo), "f"(hi)); return r;
}
__device__ __forceinline__ void upk2(u64 v, float& lo, float& hi) {
    asm("mov.b64 {%0,%1},%2;" : "=f"(lo), "=f"(hi) : "l"(v));
}
// Blackwell packed fp32x2 ops (2 flops / instruction on the fma pipe)
__device__ __forceinline__ u64 fma2(u64 a, u64 b, u64 c) {
    u64 r; asm("fma.rn.f32x2 %0,%1,%2,%3;" : "=l"(r) : "l"(a), "l"(b), "l"(c)); return r;
}
__device__ __forceinline__ u64 mul2(u64 a, u64 b) {
    u64 r; asm("mul.rn.f32x2 %0,%1,%2;" : "=l"(r) : "l"(a), "l"(b)); return r;
}

__global__ void prep_kernel(const float* __restrict__ eps) {
    int idx = blockIdx.x * blockDim.x + threadIdx.x;
    if (idx >= L_SEQ * M_DIM) return;
    int i = idx >> 7;
    int m = idx & 127;
    // eps layout [D, M, L] row-major
    float a = eps[(size_t)m * L_SEQ + i];             // d = 0
    float b = eps[(size_t)(M_DIM + m) * L_SEQ + i];   // d = 1
    g_tbl[i * 256 + m]       = a;
    g_tbl[i * 256 + 128 + m] = b - a;
}

__global__ __launch_bounds__(128)
void arqgps_kernel(const int* __restrict__ inp, float* __restrict__ out, int nrows) {
    const int r       = threadIdx.x & 7;                     // thread-in-row (8 per row)
    const int row_raw = blockIdx.x * (blockDim.x >> 3) + (threadIdx.x >> 3);
    const bool live   = (row_raw < nrows);
    const int row     = live ? row_raw : (nrows - 1);        // clamp; never early-exit (warp shuffles!)

    const float4* __restrict__ tb = reinterpret_cast<const float4*>(g_tbl); // 64 float4 / step
    const int* __restrict__ irow = inp + (size_t)row * L_SEQ;

    u64 G[8];                                   // 16 m-values as 8 packed pairs
    const u64 one2 = pk2(1.f, 1.f);
    #pragma unroll
    for (int k = 0; k < 8; k++) G[k] = one2;

    float acc = 0.f;
    int   c1  = 0;                              // count of spin==1 among s_0..s_{i-1}

    // current-step tile (this thread's 16 m: float4 indices r+8k of each half)
    float4 E[4], Dv[4];
    #pragma unroll
    for (int k = 0; k < 4; k++) { E[k] = tb[r + 8 * k]; Dv[k] = tb[32 + r + 8 * k]; }

    const float NEG_INF = __int_as_float(0xff800000);

    for (int i0 = 0; i0 < L_SEQ; i0 += 8) {
        // one input load per lane per 8 steps; broadcast below via width-8 shuffle
        int iv = __ldg(irow + i0 + r);

        #pragma unroll
        for (int j = 0; j < 8; j++) {
            const int i = i0 + j;
            const int inext = (i + 1 < L_SEQ) ? (i + 1) : (L_SEQ - 1);

            // prefetch next step's tile while computing this one
            float4 En[4], Dn[4];
            const float4* __restrict__ tn = tb + inext * 64;
            #pragma unroll
            for (int k = 0; k < 4; k++) { En[k] = tn[r + 8 * k]; Dn[k] = tn[32 + r + 8 * k]; }

            const int   s  = __shfl_sync(0xffffffffu, iv, j, 8);  // s_i for this row
            const float sf = (float)s;
            const u64   s2 = pk2(sf, sf);
            const u64   z2 = pk2(0.f, 0.f);

            u64 s0a = z2, s0b = z2, sda = z2, sdb = z2;
            #pragma unroll
            for (int k = 0; k < 4; k++) {
                u64 e0l = pk2(E[k].x,  E[k].y),  e0h = pk2(E[k].z,  E[k].w);
                u64 dl  = pk2(Dv[k].x, Dv[k].y), dh  = pk2(Dv[k].z, Dv[k].w);
                s0a = fma2(e0l, G[2 * k],     s0a);      // x0 partial
                s0b = fma2(e0h, G[2 * k + 1], s0b);
                sda = fma2(dl,  G[2 * k],     sda);      // delta partial (x1-x0)
                sdb = fma2(dh,  G[2 * k + 1], sdb);
                u64 esl = fma2(s2, dl, e0l);             // eps[s] = e0 + s*dlt
                u64 esh = fma2(s2, dh, e0h);
                G[2 * k]     = mul2(esl, G[2 * k]);      // g <- eps[s] * g
                G[2 * k + 1] = mul2(esh, G[2 * k + 1]);
            }

            float pa, pb, pc, pd;
            upk2(s0a, pa, pb); upk2(s0b, pc, pd);
            float x0 = (pa + pb) + (pc + pd);
            upk2(sda, pa, pb); upk2(sdb, pc, pd);
            float dx = (pa + pb) + (pc + pd);

            // reduce across the 8 lanes of this row (xor stays inside 8-group)
            #pragma unroll
            for (int o = 1; o < 8; o <<= 1) {
                x0 += __shfl_xor_sync(0xffffffffu, x0, o);
                dx += __shfl_xor_sync(0xffffffffu, dx, o);
            }
            const float x1 = x0 + dx;

            // exhaustion renorm (counts over s_0..s_{i-1}); selected branch never exhausted
            const float A0 = ((i - c1) >= 512) ? NEG_INF : 2.f * x0;
            const float A1 = (c1 >= 512)       ? NEG_INF : 2.f * x1;
            const float mx = fmaxf(A0, A1);
            const float t  = __expf(A0 - mx) + __expf(A1 - mx);
            const float xs = s ? x1 : x0;
            acc += xs - 0.5f * (mx + __logf(t));
            c1  += s;

            #pragma unroll
            for (int k = 0; k < 4; k++) { E[k] = En[k]; Dv[k] = Dn[k]; }
        }
    }

    if (live && r == 0) out[row] = acc;
}

extern "C" void kernel_launch(void* const* d_in, const int* in_sizes, int n_in,
                              void* d_out, int out_size) {
    // identify inputs by element count (inputs: B*1024 int32, epsilon: 2*128*1024 f32)
    const int*   inp = nullptr;
    const float* eps = nullptr;
    int rows = 0;
    if (in_sizes[0] == 2 * M_DIM * L_SEQ) {
        eps = (const float*)d_in[0];
        inp = (const int*)d_in[1];
        rows = in_sizes[1] / L_SEQ;
    } else {
        inp = (const int*)d_in[0];
        eps = (const float*)d_in[1];
        rows = in_sizes[0] / L_SEQ;
    }

    // 1) transpose epsilon into (e0, delta) step-major table
    {
        int n = L_SEQ * M_DIM;
        prep_kernel<<<(n + 255) / 256, 256>>>(eps);
    }
    // 2) main recurrence: 8 threads/row, 128-thread blocks (16 rows/block)
    {
        int rows_per_block = 128 / 8;
        int grid = (rows + rows_per_block - 1) / rows_per_block;
        arqgps_kernel<<<grid, 128>>>(inp, (float*)d_out, rows);
    }
}

// round 3
// speedup vs baseline: 1.4447x; 1.4447x over previous
#include <cuda_runtime.h>

#define L_SEQ 1024
#define M_DIM 128

// Transposed table, per step i: 1KB = 64 chunks of 16B.
// chunks 0..31:  e0[m] = eps[0,m,i]        (128 floats)
// chunks 32..63: dlt[m] = eps[1,m,i]-e0[m] (128 floats)
__device__ float g_tbl[L_SEQ * 256];

typedef unsigned long long u64;

__device__ __forceinline__ u64 pk2(float lo, float hi) {
    u64 r; asm("mov.b64 %0,{%1,%2};" : "=l"(r) : "f"(lo), "f"(hi)); return r;
}
__device__ __forceinline__ void upk2(u64 v, float& lo, float& hi) {
    asm("mov.b64 {%0,%1},%2;" : "=f"(lo), "=f"(hi) : "l"(v));
}
// Blackwell packed fp32x2 (2 flops/inst on the fma pipe)
__device__ __forceinline__ u64 fma2(u64 a, u64 b, u64 c) {
    u64 r; asm("fma.rn.f32x2 %0,%1,%2,%3;" : "=l"(r) : "l"(a), "l"(b), "l"(c)); return r;
}
__device__ __forceinline__ u64 mul2(u64 a, u64 b) {
    u64 r; asm("mul.rn.f32x2 %0,%1,%2;" : "=l"(r) : "l"(a), "l"(b)); return r;
}

__global__ void prep_kernel(const float* __restrict__ eps) {
    int idx = blockIdx.x * blockDim.x + threadIdx.x;
    if (idx >= L_SEQ * M_DIM) return;
    int i = idx >> 7;
    int m = idx & 127;
    // eps layout [D, M, L] row-major
    float a = eps[(size_t)m * L_SEQ + i];             // d = 0
    float b = eps[(size_t)(M_DIM + m) * L_SEQ + i];   // d = 1
    g_tbl[i * 256 + m]       = a;
    g_tbl[i * 256 + 128 + m] = b - a;
}

__global__ __launch_bounds__(128, 8)
void arqgps_kernel(const int* __restrict__ inp, float* __restrict__ out, int nrows) {
    const int r       = threadIdx.x & 15;                    // thread-in-row (16 per row)
    const int row_raw = blockIdx.x * (blockDim.x >> 4) + (threadIdx.x >> 4);
    const bool live   = (row_raw < nrows);
    const int row     = live ? row_raw : (nrows - 1);        // clamp; never early-exit (shuffles!)

    const ulonglong2* __restrict__ tb = reinterpret_cast<const ulonglong2*>(g_tbl); // 64/step
    const int* __restrict__ irow = inp + (size_t)row * L_SEQ;

    const u64 one2 = pk2(1.f, 1.f);
    u64 G[4];                                    // 8 m-values as 4 packed pairs
    #pragma unroll
    for (int k = 0; k < 4; k++) G[k] = one2;

    float acc = 0.f;
    int   c1  = 0;                               // count of spin==1 among s_0..s_{i-1}

    // current-step tile: this thread's 8 m live in chunks r, 16+r (e0) / 32+r, 48+r (dlt)
    ulonglong2 E0 = tb[r], E1 = tb[16 + r], D0 = tb[32 + r], D1 = tb[48 + r];

    int iv = __ldg(irow + r);                    // s for steps 0..15 (lane r holds step r)

    for (int i0 = 0; i0 < L_SEQ; i0 += 16) {
        int ivn = (i0 + 16 < L_SEQ) ? __ldg(irow + i0 + 16 + r) : 0;

        #pragma unroll
        for (int j = 0; j < 16; j++) {
            const int i = i0 + j;
            const int inext = (i + 1 < L_SEQ) ? (i + 1) : (L_SEQ - 1);

            // prefetch next step's tile
            const ulonglong2* __restrict__ tn = tb + inext * 64;
            ulonglong2 En0 = tn[r], En1 = tn[16 + r], Dn0 = tn[32 + r], Dn1 = tn[48 + r];

            const int   s  = __shfl_sync(0xffffffffu, iv, j, 16);  // s_i for this row
            const float sf = (float)s;
            const u64   s2 = pk2(sf, sf);

            // dx partials: sum_m dlt[m]*g[m]
            u64 sda = mul2(D0.x, G[0]);
            u64 sdb = mul2(D0.y, G[1]);
            sda = fma2(D1.x, G[2], sda);
            sdb = fma2(D1.y, G[3], sdb);

            // g <- (e0 + s*dlt) * g
            u64 es;
            es = fma2(s2, D0.x, E0.x); G[0] = mul2(es, G[0]);
            es = fma2(s2, D0.y, E0.y); G[1] = mul2(es, G[1]);
            es = fma2(s2, D1.x, E1.x); G[2] = mul2(es, G[2]);
            es = fma2(s2, D1.y, E1.y); G[3] = mul2(es, G[3]);

            float pa, pb, pc, pd;
            upk2(sda, pa, pb); upk2(sdb, pc, pd);
            float dx = (pa + pb) + (pc + pd);

            // reduce dx across the 16 lanes of this row (xor<16 stays in-group)
            #pragma unroll
            for (int o = 1; o < 16; o <<= 1)
                dx += __shfl_xor_sync(0xffffffffu, dx, o);

            // contribution = min(0, +-dx) - 0.5*log(1+exp(-2|dx|)); 0 if other branch dead
            const float sgn = s ? dx : -dx;
            const float contrib = fminf(0.f, sgn)
                                - 0.5f * __logf(1.f + __expf(-2.f * fabsf(dx)));
            const bool dead_other = s ? ((i - c1) >= 512) : (c1 >= 512);
            acc += dead_other ? 0.f : contrib;
            c1  += s;

            E0 = En0; E1 = En1; D0 = Dn0; D1 = Dn1;
        }
        iv = ivn;
    }

    if (live && r == 0) out[row] = acc;
}

extern "C" void kernel_launch(void* const* d_in, const int* in_sizes, int n_in,
                              void* d_out, int out_size) {
    // identify inputs by element count (inputs: B*1024 int32, epsilon: 2*128*1024 f32)
    const int*   inp = nullptr;
    const float* eps = nullptr;
    int rows = 0;
    if (in_sizes[0] == 2 * M_DIM * L_SEQ) {
        eps = (const float*)d_in[0];
        inp = (const int*)d_in[1];
        rows = in_sizes[1] / L_SEQ;
    } else {
        inp = (const int*)d_in[0];
        eps = (const float*)d_in[1];
        rows = in_sizes[0] / L_SEQ;
    }

    // 1) transpose epsilon into (e0, delta) step-major table
    {
        int n = L_SEQ * M_DIM;
        prep_kernel<<<(n + 255) / 256, 256>>>(eps);
    }
    // 2) main recurrence: 16 threads/row, 128-thread blocks (8 rows/block)
    {
        int rows_per_block = 128 / 16;
        int grid = (rows + rows_per_block - 1) / rows_per_block;
        arqgps_kernel<<<grid, 128>>>(inp, (float*)d_out, rows);
    }
}

// round 4
// speedup vs baseline: 1.8320x; 1.2681x over previous
#include <cuda_runtime.h>

#define L_SEQ 1024
#define M_DIM 128

// Transposed table, per step i (64 x 16B chunks = 1KB):
//   chunks 0..31:  e0[m]  = eps[0,m,i]
//   chunks 32..63: dlt[m] = eps[1,m,i] - eps[0,m,i]
// Padded to 1025 steps so "next step" prefetch never needs a clamp branch.
__device__ float g_tbl[(L_SEQ + 1) * 256];

typedef unsigned long long u64;

__device__ __forceinline__ u64 pk2(float lo, float hi) {
    u64 r; asm("mov.b64 %0,{%1,%2};" : "=l"(r) : "f"(lo), "f"(hi)); return r;
}
__device__ __forceinline__ void upk2(u64 v, float& lo, float& hi) {
    asm("mov.b64 {%0,%1},%2;" : "=f"(lo), "=f"(hi) : "l"(v));
}
// Blackwell packed fp32x2 (2 flops/inst on the fma pipe)
__device__ __forceinline__ u64 fma2(u64 a, u64 b, u64 c) {
    u64 r; asm("fma.rn.f32x2 %0,%1,%2,%3;" : "=l"(r) : "l"(a), "l"(b), "l"(c)); return r;
}
__device__ __forceinline__ u64 mul2(u64 a, u64 b) {
    u64 r; asm("mul.rn.f32x2 %0,%1,%2;" : "=l"(r) : "l"(a), "l"(b)); return r;
}

__global__ void prep_kernel(const float* __restrict__ eps) {
    int idx = blockIdx.x * blockDim.x + threadIdx.x;
    if (idx >= L_SEQ * M_DIM) return;
    int i = idx >> 7;
    int m = idx & 127;
    // eps layout [D, M, L] row-major
    float a = eps[(size_t)m * L_SEQ + i];             // d = 0
    float b = eps[(size_t)(M_DIM + m) * L_SEQ + i];   // d = 1
    g_tbl[i * 256 + m]       = a;
    g_tbl[i * 256 + 128 + m] = b - a;
}

__global__ __launch_bounds__(128, 8)
void arqgps_kernel(const int* __restrict__ inp, float* __restrict__ out, int nrows) {
    const unsigned FULL = 0xffffffffu;
    const int lane    = threadIdx.x & 31;
    const int r       = lane & 15;                           // thread-in-row (16 per row)
    const int gbase   = lane & 16;                           // 16-group base within warp
    const int row_raw = blockIdx.x * (blockDim.x >> 4) + (threadIdx.x >> 4);
    const bool live   = (row_raw < nrows);
    const int row     = live ? row_raw : (nrows - 1);        // clamp; never early-exit

    const ulonglong2* __restrict__ tb = reinterpret_cast<const ulonglong2*>(g_tbl);
    const int* __restrict__ irow = inp + (size_t)row * L_SEQ;

    const u64 one2 = pk2(1.f, 1.f);
    u64 G[4];                                    // 8 m-values as 4 packed pairs
    #pragma unroll
    for (int k = 0; k < 4; k++) G[k] = one2;

    float acc = 0.f;
    int   c1b = 0;                               // #spin==1 among steps < current super-block

    // lane -> which step of an 8-batch this lane finalizes after reduce-scatter
    const int jm = 4 * (r & 1) + 2 * ((r >> 1) & 1) + ((r >> 2) & 1);
    const bool b0 = (r & 1), b1 = (r & 2), b2 = (r & 4);

    // current-step tile (step 0)
    ulonglong2 E0 = tb[r], E1 = tb[16 + r], D0 = tb[32 + r], D1 = tb[48 + r];

    int iv = __ldg(irow + r);                                // s for steps 0..15
    unsigned bits = (__ballot_sync(FULL, iv & 1) >> gbase) & 0xffffu;

    for (int i0 = 0; i0 < L_SEQ; i0 += 16) {
        const int ivn = (i0 + 16 < L_SEQ) ? __ldg(irow + i0 + 16 + r) : 0;
        const unsigned bitsn = (__ballot_sync(FULL, ivn & 1) >> gbase) & 0xffffu;
        const unsigned bcomb = bits | (bitsn << 16);         // 17+ bits of lookahead
        const ulonglong2* __restrict__ bb = tb + (size_t)i0 * 64;

        #pragma unroll
        for (int hb = 0; hb < 2; hb++) {
            const int off = hb * 8;
            float dxp[8];

            #pragma unroll
            for (int t = 0; t < 8; t++) {
                const int k = off + t;
                // prefetch next step's tile (immediate offsets off bb)
                ulonglong2 nE0 = bb[(k + 1) * 64 + r];
                ulonglong2 nE1 = bb[(k + 1) * 64 + 16 + r];
                ulonglong2 nD0 = bb[(k + 1) * 64 + 32 + r];
                ulonglong2 nD1 = bb[(k + 1) * 64 + 48 + r];

                // dx partial: sum_m dlt[m]*g[m] over this lane's 8 m
                u64 sa = mul2(D0.x, G[0]);
                u64 sb = mul2(D0.y, G[1]);
                sa = fma2(D1.x, G[2], sa);
                sb = fma2(D1.y, G[3], sb);
                float pa, pb, pc, pd;
                upk2(sa, pa, pb); upk2(sb, pc, pd);
                dxp[t] = (pa + pb) + (pc + pd);

                // g <- (e0 + s*dlt) * g
                const float sf = (float)((bcomb >> k) & 1u);
                const u64 s2 = pk2(sf, sf);
                u64 es;
                es = fma2(s2, D0.x, E0.x); G[0] = mul2(es, G[0]);
                es = fma2(s2, D0.y, E0.y); G[1] = mul2(es, G[1]);
                es = fma2(s2, D1.x, E1.x); G[2] = mul2(es, G[2]);
                es = fma2(s2, D1.y, E1.y); G[3] = mul2(es, G[3]);

                E0 = nE0; E1 = nE1; D0 = nD0; D1 = nD1;
            }

            // butterfly reduce-scatter over the 16 lanes of this row:
            // after 4 rounds, this lane holds the full dx of step off+jm (dup x2 across bit3)
            float w[4], u[2], z;
            #pragma unroll
            for (int t = 0; t < 4; t++) {
                float send = b0 ? dxp[t] : dxp[t + 4];
                float o = __shfl_xor_sync(FULL, send, 1);
                w[t] = (b0 ? dxp[t + 4] : dxp[t]) + o;
            }
            #pragma unroll
            for (int t = 0; t < 2; t++) {
                float send = b1 ? w[t] : w[t + 2];
                float o = __shfl_xor_sync(FULL, send, 2);
                u[t] = (b1 ? w[t + 2] : w[t]) + o;
            }
            {
                float send = b2 ? u[0] : u[1];
                float o = __shfl_xor_sync(FULL, send, 4);
                z = (b2 ? u[1] : u[0]) + o;
            }
            const float dxt = z + __shfl_xor_sync(FULL, z, 8);

            // this lane's step: i = i0 + off + jm
            const int kk = off + jm;
            const int i  = i0 + kk;
            const int s  = (bits >> kk) & 1;
            const int c1i = c1b + __popc(bits & ((1u << kk) - 1u));

            const float sgn = s ? dxt : -dxt;
            const float contrib = fminf(0.f, sgn)
                                - 0.5f * __logf(1.f + __expf(-2.f * fabsf(dxt)));
            const bool dead_other = s ? ((i - c1i) >= 512) : (c1i >= 512);
            acc += dead_other ? 0.f : contrib;
        }

        c1b += __popc(bits);
        bits = bitsn;
        iv = ivn;
    }

    // each contribution counted twice (both 8-lane halves) -> 0.5x at the end
    #pragma unroll
    for (int o = 1; o < 16; o <<= 1)
        acc += __shfl_xor_sync(FULL, acc, o);

    if (live && r == 0) out[row] = 0.5f * acc;
}

extern "C" void kernel_launch(void* const* d_in, const int* in_sizes, int n_in,
                              void* d_out, int out_size) {
    // identify inputs by element count (inputs: B*1024 int32, epsilon: 2*128*1024 f32)
    const int*   inp = nullptr;
    const float* eps = nullptr;
    int rows = 0;
    if (in_sizes[0] == 2 * M_DIM * L_SEQ) {
        eps = (const float*)d_in[0];
        inp = (const int*)d_in[1];
        rows = in_sizes[1] / L_SEQ;
    } else {
        inp = (const int*)d_in[0];
        eps = (const float*)d_in[1];
        rows = in_sizes[0] / L_SEQ;
    }

    // 1) transpose epsilon into (e0, delta) step-major table
    {
        int n = L_SEQ * M_DIM;
        prep_kernel<<<(n + 255) / 256, 256>>>(eps);
    }
    // 2) main recurrence: 16 threads/row, 128-thread blocks (8 rows/block)
    {
        int rows_per_block = 128 / 16;
        int grid = (rows + rows_per_block - 1) / rows_per_block;
        arqgps_kernel<<<grid, 128>>>(inp, (float*)d_out, rows);
    }
}